// round 4
// baseline (speedup 1.0000x reference)
#include <cuda_runtime.h>
#include <cuda_bf16.h>
#include <cstdint>

// Problem constants (1, 768, 128, 128)
#define C_DIM 768
#define N_DIM 16384

// ---------------- GEMM tiling (fp8 mma.sync m16n8k32) ----------------
#define BM 128              // CTA tile M
#define BN 256              // CTA tile N
#define KC 128              // K elems (bytes) per chunk = 128B/row
#define NCHUNK (C_DIM / KC) // 6
#define NSTAGE 4

#define A_STAGE_BYTES (BM * 128)                       // 16384
#define B_STAGE_BYTES (BN * 128)                       // 32768
#define STAGE_BYTES (A_STAGE_BYTES + B_STAGE_BYTES)    // 49152
#define SMAX_OFF (NSTAGE * STAGE_BYTES)                // 196608
#define SMEM_TOTAL (SMAX_OFF + 1024 + 64)

// ---------------- scratch (no allocations allowed) ----------------
__device__ float g_inv_r[N_DIM];
__device__ float g_inv_s[N_DIM];
__device__ __nv_bfloat16 g_A[(size_t)N_DIM * C_DIM];    // normalized F_r bf16 (rescue)
__device__ __nv_bfloat16 g_B[(size_t)N_DIM * C_DIM];    // normalized F_s bf16 (rescue)
__device__ unsigned char g_A8[(size_t)N_DIM * C_DIM];   // normalized F_r e4m3
__device__ unsigned char g_B8[(size_t)N_DIM * C_DIM];   // normalized F_s e4m3
__device__ unsigned long long g_rowarg[N_DIM];          // (fkey(max)<<32) | argmax_col
__device__ float g_best[N_DIM];                         // exact rescored max

__device__ __forceinline__ unsigned int fkey(float f) {
    unsigned int u = __float_as_uint(f);
    return (u & 0x80000000u) ? ~u : (u | 0x80000000u);
}
__device__ __forceinline__ uint32_t smem_u32(const void* p) {
    return (uint32_t)__cvta_generic_to_shared(p);
}

#define LDSM4(r0, r1, r2, r3, addr) \
    asm volatile("ldmatrix.sync.aligned.m8n8.x4.shared.b16 {%0,%1,%2,%3}, [%4];" \
                 : "=r"(r0), "=r"(r1), "=r"(r2), "=r"(r3) : "r"(addr))

// ---------------- init ----------------
__global__ void init_rowmax_kernel() {
    int i = blockIdx.x * blockDim.x + threadIdx.x;
    if (i < N_DIM) g_rowarg[i] = 0ull;
}

// ---------------- inverse column norms: X is [C][N], norm over C ----------------
__global__ void colnorm_kernel(const float* __restrict__ X, int which) {
    __shared__ float red[256];
    int tid = threadIdx.x;
    int n = blockIdx.x * 64 + (tid & 63);
    int part = tid >> 6;
    const int CP = C_DIM / 4;
    const float* p = X + (size_t)part * CP * N_DIM + n;
    float s = 0.f;
    #pragma unroll 4
    for (int c = 0; c < CP; ++c) {
        float v = p[(size_t)c * N_DIM];
        s += v * v;
    }
    red[tid] = s;
    __syncthreads();
    if (tid < 64) {
        float t = red[tid] + red[tid + 64] + red[tid + 128] + red[tid + 192];
        float inv = 1.0f / fmaxf(sqrtf(t), 1e-12f);
        if (which) g_inv_s[n] = inv; else g_inv_r[n] = inv;
    }
}

// -------- transpose + normalize: [C][N] -> [N][C], bf16 + e4m3 outputs --------
__global__ void transpose_scale_kernel(const float* __restrict__ X, int which) {
    __shared__ float tile[32][33];
    const float* inv = which ? g_inv_s : g_inv_r;
    __nv_bfloat16* T = which ? g_B : g_A;
    unsigned char* T8 = which ? g_B8 : g_A8;
    int n0 = blockIdx.x * 32;
    int c0 = blockIdx.y * 32;
    int tx = threadIdx.x, ty = threadIdx.y;
    #pragma unroll
    for (int j = ty; j < 32; j += 8)
        tile[j][tx] = X[(size_t)(c0 + j) * N_DIM + n0 + tx];
    __syncthreads();
    #pragma unroll
    for (int j = ty; j < 32; j += 8) {
        int n = n0 + j;
        float iv = inv[n];
        T[(size_t)n * C_DIM + c0 + tx] = __float2bfloat16(tile[tx][j] * iv);
        if (tx < 16) {
            float lo = tile[2 * tx][j] * iv;
            float hi = tile[2 * tx + 1][j] * iv;
            unsigned short u;
            asm("cvt.rn.satfinite.e4m3x2.f32 %0, %1, %2;" : "=h"(u) : "f"(hi), "f"(lo));
            *(unsigned short*)(T8 + (size_t)n * C_DIM + c0 + 2 * tx) = u;
        }
    }
}

// ---------------- fused fp8 GEMM + row-(max,argmax) ----------------
// smem rows of 128B; 16B chunk ch swizzled: off = row*128 + ((ch ^ (row&7)) << 4)
__device__ __forceinline__ void load_stage(uint32_t smem_base, int stage, int chunk,
                                           const unsigned char* gA,
                                           const unsigned char* gB, int tid) {
    uint32_t sA = smem_base + stage * STAGE_BYTES;
    uint32_t sB = sA + A_STAGE_BYTES;
    const unsigned char* srcA = gA + (size_t)chunk * KC;
    const unsigned char* srcB = gB + (size_t)chunk * KC;
    #pragma unroll
    for (int i = 0; i < 4; ++i) {            // A: 128 rows x 8 chunks = 1024
        int c = i * 256 + tid;
        int row = c >> 3, ch = c & 7;
        uint32_t off = row * 128 + ((ch ^ (row & 7)) << 4);
        const unsigned char* p = srcA + (size_t)row * C_DIM + ch * 16;
        asm volatile("cp.async.cg.shared.global [%0], [%1], 16;" :: "r"(sA + off), "l"(p));
    }
    #pragma unroll
    for (int i = 0; i < 8; ++i) {            // B: 256 rows x 8 chunks = 2048
        int c = i * 256 + tid;
        int row = c >> 3, ch = c & 7;
        uint32_t off = row * 128 + ((ch ^ (row & 7)) << 4);
        const unsigned char* p = srcB + (size_t)row * C_DIM + ch * 16;
        asm volatile("cp.async.cg.shared.global [%0], [%1], 16;" :: "r"(sB + off), "l"(p));
    }
    asm volatile("cp.async.commit_group;");
}

__global__ void __launch_bounds__(256, 1) nnfm_gemm_qmma() {
    extern __shared__ __align__(1024) char smem[];
    uint32_t smem_base = smem_u32(smem);
    unsigned long long* smax = (unsigned long long*)(smem + SMAX_OFF);

    int tid = threadIdx.x;
    int wid = tid >> 5;
    int lane = tid & 31;
    int tileM = blockIdx.y, tileN = blockIdx.x;

    const unsigned char* gA = g_A8 + (size_t)tileM * BM * C_DIM;
    const unsigned char* gB = g_B8 + (size_t)tileN * BN * C_DIM;

    // warp grid: 2 (M) x 4 (N); warp tile 64x64 = 4x8 frags of m16n8
    int mb = (wid >> 2) * 64;
    int nb = (wid & 3) * 64;

    // ldmatrix lane addresses (swizzle folded); byte layout identical to bf16 k16 case
    int grpRowA = (lane & 7) + ((lane >> 3) & 1) * 8;
    uint32_t aKbit = (uint32_t)(lane >> 4) << 4;
    uint32_t baseA[4];
    #pragma unroll
    for (int mi = 0; mi < 4; ++mi) {
        int r = mb + mi * 16 + grpRowA;
        baseA[mi] = (smem_base + r * 128 + ((r & 7) << 4)) ^ aKbit;
    }
    int grpRowB = (lane & 7) + ((lane >> 4) << 3);
    uint32_t bKbit = (uint32_t)((lane >> 3) & 1) << 4;
    uint32_t baseB[4];
    #pragma unroll
    for (int p = 0; p < 4; ++p) {
        int r = nb + p * 16 + grpRowB;
        baseB[p] = (smem_base + A_STAGE_BYTES + r * 128 + ((r & 7) << 4)) ^ bKbit;
    }

    float acc[4][8][4];
    #pragma unroll
    for (int mi = 0; mi < 4; ++mi)
        #pragma unroll
        for (int ni = 0; ni < 8; ++ni)
            #pragma unroll
            for (int q = 0; q < 4; ++q) acc[mi][ni][q] = 0.f;

    #pragma unroll
    for (int s = 0; s < NSTAGE - 1; ++s) load_stage(smem_base, s, s, gA, gB, tid);

    for (int k = 0; k < NCHUNK; ++k) {
        int st = k & (NSTAGE - 1);
        uint32_t stOff = st * STAGE_BYTES;
        asm volatile("cp.async.wait_group %0;" :: "n"(NSTAGE - 2));
        __syncthreads();

        if (k + NSTAGE - 1 < NCHUNK)
            load_stage(smem_base, (k + NSTAGE - 1) & (NSTAGE - 1), k + NSTAGE - 1, gA, gB, tid);
        else
            asm volatile("cp.async.commit_group;");

        #pragma unroll
        for (int ki = 0; ki < 4; ++ki) {          // K=32 fp8 per step, 32B stride
            uint32_t kx = (uint32_t)ki << 5;
            uint32_t a[4][4], b[8][2];
            #pragma unroll
            for (int mi = 0; mi < 4; ++mi)
                LDSM4(a[mi][0], a[mi][1], a[mi][2], a[mi][3], (baseA[mi] + stOff) ^ kx);
            #pragma unroll
            for (int p = 0; p < 4; ++p)
                LDSM4(b[2*p][0], b[2*p][1], b[2*p+1][0], b[2*p+1][1], (baseB[p] + stOff) ^ kx);
            #pragma unroll
            for (int mi = 0; mi < 4; ++mi)
                #pragma unroll
                for (int ni = 0; ni < 8; ++ni) {
                    float* c = acc[mi][ni];
                    asm volatile(
                        "mma.sync.aligned.m16n8k32.row.col.f32.e4m3.e4m3.f32 "
                        "{%0,%1,%2,%3}, {%4,%5,%6,%7}, {%8,%9}, {%0,%1,%2,%3};"
                        : "+f"(c[0]), "+f"(c[1]), "+f"(c[2]), "+f"(c[3])
                        : "r"(a[mi][0]), "r"(a[mi][1]), "r"(a[mi][2]), "r"(a[mi][3]),
                          "r"(b[ni][0]), "r"(b[ni][1]));
                }
        }
    }

    // ---- epilogue: per-row (max, argmax col) of this 128x256 tile ----
    __syncthreads();
    if (tid < BM) smax[tid] = 0ull;
    __syncthreads();

    int colBase = tileN * BN + nb + (lane & 3) * 2;
    #pragma unroll
    for (int mi = 0; mi < 4; ++mi) {
        float m0 = -3.402823466e38f, m1 = -3.402823466e38f;
        int c0i = 0, c1i = 0;
        #pragma unroll
        for (int ni = 0; ni < 8; ++ni) {
            int cc = colBase + ni * 8;
            if (acc[mi][ni][0] > m0) { m0 = acc[mi][ni][0]; c0i = cc; }
            if (acc[mi][ni][1] > m0) { m0 = acc[mi][ni][1]; c0i = cc + 1; }
            if (acc[mi][ni][2] > m1) { m1 = acc[mi][ni][2]; c1i = cc; }
            if (acc[mi][ni][3] > m1) { m1 = acc[mi][ni][3]; c1i = cc + 1; }
        }
        #pragma unroll
        for (int d = 1; d <= 2; d <<= 1) {
            float ov = __shfl_xor_sync(0xffffffffu, m0, d);
            int oc = __shfl_xor_sync(0xffffffffu, c0i, d);
            if (ov > m0) { m0 = ov; c0i = oc; }
            ov = __shfl_xor_sync(0xffffffffu, m1, d);
            oc = __shfl_xor_sync(0xffffffffu, c1i, d);
            if (ov > m1) { m1 = ov; c1i = oc; }
        }
        if ((lane & 3) == 0) {
            int r = mb + mi * 16 + (lane >> 2);
            atomicMax(&smax[r], ((unsigned long long)fkey(m0) << 32) | (unsigned int)c0i);
            atomicMax(&smax[r + 8], ((unsigned long long)fkey(m1) << 32) | (unsigned int)c1i);
        }
    }
    __syncthreads();
    if (tid < BM) atomicMax(&g_rowarg[tileM * BM + tid], smax[tid]);
}

// ---------------- rescue: exact bf16->fp32 rescore of selected pairs ----------------
__global__ void rescue_kernel() {
    int warp = (blockIdx.x * blockDim.x + threadIdx.x) >> 5;
    int lane = threadIdx.x & 31;
    int row = warp;
    unsigned int col = (unsigned int)(g_rowarg[row] & 0xffffffffu);
    const uint4* pa = (const uint4*)(g_A + (size_t)row * C_DIM);
    const uint4* pb = (const uint4*)(g_B + (size_t)col * C_DIM);
    float s = 0.f;
    #pragma unroll
    for (int i = 0; i < 3; ++i) {
        uint4 wa = pa[i * 32 + lane];
        uint4 wb = pb[i * 32 + lane];
        const unsigned int* ua = (const unsigned int*)&wa;
        const unsigned int* ub = (const unsigned int*)&wb;
        #pragma unroll
        for (int j = 0; j < 4; ++j) {
            float al = __uint_as_float(ua[j] << 16);
            float ah = __uint_as_float(ua[j] & 0xffff0000u);
            float bl = __uint_as_float(ub[j] << 16);
            float bh = __uint_as_float(ub[j] & 0xffff0000u);
            s += al * bl + ah * bh;
        }
    }
    #pragma unroll
    for (int d = 16; d > 0; d >>= 1) s += __shfl_xor_sync(0xffffffffu, s, d);
    if (lane == 0) g_best[row] = s;
}

// ---------------- final: loss = mean(1 - best) ----------------
__global__ void final_reduce_kernel(float* __restrict__ out) {
    __shared__ float red[256];
    int tid = threadIdx.x;
    float s = 0.f;
    for (int i = tid; i < N_DIM; i += 256) s += 1.0f - g_best[i];
    red[tid] = s;
    __syncthreads();
    for (int off = 128; off > 0; off >>= 1) {
        if (tid < off) red[tid] += red[tid + off];
        __syncthreads();
    }
    if (tid == 0) out[0] = red[0] / (float)N_DIM;
}

// ---------------- launch ----------------
extern "C" void kernel_launch(void* const* d_in, const int* in_sizes, int n_in,
                              void* d_out, int out_size) {
    const float* F_r = (const float*)d_in[0];
    const float* F_s = (const float*)d_in[1];

    cudaFuncSetAttribute(nnfm_gemm_qmma, cudaFuncAttributeMaxDynamicSharedMemorySize, SMEM_TOTAL);

    init_rowmax_kernel<<<N_DIM / 256, 256>>>();
    colnorm_kernel<<<N_DIM / 64, 256>>>(F_r, 0);
    colnorm_kernel<<<N_DIM / 64, 256>>>(F_s, 1);

    dim3 tb(32, 8);
    dim3 tg(N_DIM / 32, C_DIM / 32);
    transpose_scale_kernel<<<tg, tb>>>(F_r, 0);
    transpose_scale_kernel<<<tg, tb>>>(F_s, 1);

    dim3 gg(N_DIM / BN, N_DIM / BM);   // 64 x 128
    nnfm_gemm_qmma<<<gg, 256, SMEM_TOTAL>>>();

    rescue_kernel<<<N_DIM / 8, 256>>>();
    final_reduce_kernel<<<1, 256>>>((float*)d_out);
}

// round 5
// speedup vs baseline: 1.2191x; 1.2191x over previous
#include <cuda_runtime.h>
#include <cuda_bf16.h>
#include <cstdint>

// Problem constants (1, 768, 128, 128)
#define C_DIM 768
#define N_DIM 16384

// ---------------- GEMM tiling (bf16 mma.sync m16n8k16) ----------------
#define BM 128            // CTA tile M
#define BN 256            // CTA tile N
#define KC 64             // K per chunk = 128 bytes/row
#define NCHUNK (C_DIM / KC)   // 12
#define NSTAGE 4

#define A_STAGE_BYTES (BM * 128)              // 16384
#define B_STAGE_BYTES (BN * 128)              // 32768
#define STAGE_BYTES (A_STAGE_BYTES + B_STAGE_BYTES)   // 49152
#define SMAX_OFF (NSTAGE * STAGE_BYTES)       // 196608
#define SMEM_TOTAL (SMAX_OFF + 512)

// ---------------- scratch (no allocations allowed) ----------------
__device__ float g_inv_r[N_DIM];
__device__ float g_inv_s[N_DIM];
__device__ __nv_bfloat16 g_A[(size_t)N_DIM * C_DIM];   // normalized F_r, [n][c]
__device__ __nv_bfloat16 g_B[(size_t)N_DIM * C_DIM];   // normalized F_s, [m][c]
__device__ unsigned int g_rowmax[N_DIM];               // monotonic float keys

__device__ __forceinline__ unsigned int fkey(float f) {
    unsigned int u = __float_as_uint(f);
    return (u & 0x80000000u) ? ~u : (u | 0x80000000u);
}
__device__ __forceinline__ uint32_t smem_u32(const void* p) {
    return (uint32_t)__cvta_generic_to_shared(p);
}

#define LDSM4(r0, r1, r2, r3, addr) \
    asm volatile("ldmatrix.sync.aligned.m8n8.x4.shared.b16 {%0,%1,%2,%3}, [%4];" \
                 : "=r"(r0), "=r"(r1), "=r"(r2), "=r"(r3) : "r"(addr))

// ---------------- init row maxes ----------------
__global__ void init_rowmax_kernel() {
    int i = blockIdx.x * blockDim.x + threadIdx.x;
    if (i < N_DIM) g_rowmax[i] = 0u;
}

// ---------------- inverse column norms: X is [C][N], norm over C ----------------
__global__ void colnorm_kernel(const float* __restrict__ X, int which) {
    __shared__ float red[256];
    int tid = threadIdx.x;
    int n = blockIdx.x * 64 + (tid & 63);
    int part = tid >> 6;
    const int CP = C_DIM / 4;
    const float* p = X + (size_t)part * CP * N_DIM + n;
    float s = 0.f;
    #pragma unroll 4
    for (int c = 0; c < CP; ++c) {
        float v = p[(size_t)c * N_DIM];
        s += v * v;
    }
    red[tid] = s;
    __syncthreads();
    if (tid < 64) {
        float t = red[tid] + red[tid + 64] + red[tid + 128] + red[tid + 192];
        float inv = 1.0f / fmaxf(sqrtf(t), 1e-12f);
        if (which) g_inv_s[n] = inv; else g_inv_r[n] = inv;
    }
}

// -------- transpose + normalize + bf16: [C][N] -> [N][C], 64x64 tiles, float4 ----
__global__ void __launch_bounds__(256) transpose_scale_kernel(const float* __restrict__ X,
                                                              int which) {
    __shared__ float tf[64][65];
    const float* inv = which ? g_inv_s : g_inv_r;
    __nv_bfloat16* T = which ? g_B : g_A;
    int n0 = blockIdx.x * 64;
    int c0 = blockIdx.y * 64;
    int t = threadIdx.x;

    #pragma unroll
    for (int i = 0; i < 4; ++i) {
        int idx = i * 256 + t;
        int row = idx >> 4;            // c offset 0..63
        int v4 = idx & 15;             // float4 index within row
        float4 v = *(const float4*)(X + (size_t)(c0 + row) * N_DIM + n0 + v4 * 4);
        tf[row][v4 * 4 + 0] = v.x;
        tf[row][v4 * 4 + 1] = v.y;
        tf[row][v4 * 4 + 2] = v.z;
        tf[row][v4 * 4 + 3] = v.w;
    }
    __syncthreads();

    #pragma unroll
    for (int j = 0; j < 8; ++j) {
        int idx = j * 256 + t;
        int nn = idx >> 5;             // n offset 0..63
        int p = idx & 31;              // bf16 pair within the 64 c's
        int n = n0 + nn;
        float iv = inv[n];
        __nv_bfloat162 h = __floats2bfloat162_rn(tf[2 * p][nn] * iv, tf[2 * p + 1][nn] * iv);
        *(__nv_bfloat162*)(T + (size_t)n * C_DIM + c0 + 2 * p) = h;
    }
}

// ---------------- fused GEMM + row-max ----------------
// smem rows of 128B; 16B chunk ch swizzled: off = row*128 + ((ch ^ (row&7)) << 4)
__device__ __forceinline__ void load_stage(uint32_t smem_base, int stage, int chunk,
                                           const __nv_bfloat16* gA,
                                           const __nv_bfloat16* gB, int tid) {
    uint32_t sA = smem_base + stage * STAGE_BYTES;
    uint32_t sB = sA + A_STAGE_BYTES;
    const __nv_bfloat16* srcA = gA + chunk * KC;
    const __nv_bfloat16* srcB = gB + chunk * KC;
    #pragma unroll
    for (int i = 0; i < 4; ++i) {            // A: 128 rows x 8 chunks = 1024
        int c = i * 256 + tid;
        int row = c >> 3, ch = c & 7;
        uint32_t off = row * 128 + ((ch ^ (row & 7)) << 4);
        const __nv_bfloat16* p = srcA + (size_t)row * C_DIM + ch * 8;
        asm volatile("cp.async.cg.shared.global [%0], [%1], 16;" :: "r"(sA + off), "l"(p));
    }
    #pragma unroll
    for (int i = 0; i < 8; ++i) {            // B: 256 rows x 8 chunks = 2048
        int c = i * 256 + tid;
        int row = c >> 3, ch = c & 7;
        uint32_t off = row * 128 + ((ch ^ (row & 7)) << 4);
        const __nv_bfloat16* p = srcB + (size_t)row * C_DIM + ch * 8;
        asm volatile("cp.async.cg.shared.global [%0], [%1], 16;" :: "r"(sB + off), "l"(p));
    }
    asm volatile("cp.async.commit_group;");
}

__global__ void __launch_bounds__(256, 1) nnfm_gemm_hmma() {
    extern __shared__ __align__(1024) char smem[];
    uint32_t smem_base = smem_u32(smem);
    unsigned int* smax = (unsigned int*)(smem + SMAX_OFF);

    int tid = threadIdx.x;
    int wid = tid >> 5;
    int lane = tid & 31;
    int tileM = blockIdx.y, tileN = blockIdx.x;

    const __nv_bfloat16* gA = g_A + (size_t)tileM * BM * C_DIM;
    const __nv_bfloat16* gB = g_B + (size_t)tileN * BN * C_DIM;

    // warp grid: 2 (M) x 4 (N); warp tile 64x64 = 4x8 frags of m16n8
    int mb = (wid >> 2) * 64;
    int nb = (wid & 3) * 64;

    // ldmatrix lane addresses with swizzle folded
    int grpRowA = (lane & 7) + ((lane >> 3) & 1) * 8;
    uint32_t aKbit = (uint32_t)(lane >> 4) << 4;
    uint32_t baseA[4];
    #pragma unroll
    for (int mi = 0; mi < 4; ++mi) {
        int r = mb + mi * 16 + grpRowA;
        baseA[mi] = (smem_base + r * 128 + ((r & 7) << 4)) ^ aKbit;
    }
    int grpRowB = (lane & 7) + ((lane >> 4) << 3);
    uint32_t bKbit = (uint32_t)((lane >> 3) & 1) << 4;
    uint32_t baseB[4];
    #pragma unroll
    for (int p = 0; p < 4; ++p) {
        int r = nb + p * 16 + grpRowB;
        baseB[p] = (smem_base + A_STAGE_BYTES + r * 128 + ((r & 7) << 4)) ^ bKbit;
    }

    float acc[4][8][4];
    #pragma unroll
    for (int mi = 0; mi < 4; ++mi)
        #pragma unroll
        for (int ni = 0; ni < 8; ++ni)
            #pragma unroll
            for (int q = 0; q < 4; ++q) acc[mi][ni][q] = 0.f;

    #pragma unroll
    for (int s = 0; s < NSTAGE - 1; ++s) load_stage(smem_base, s, s, gA, gB, tid);

    uint32_t a[2][4][4], b[2][8][2];   // double-buffered fragments

    for (int k = 0; k < NCHUNK; ++k) {
        int st = k & (NSTAGE - 1);
        uint32_t stOff = st * STAGE_BYTES;
        asm volatile("cp.async.wait_group %0;" :: "n"(NSTAGE - 2));
        __syncthreads();

        // prefetch kstep 0 fragments
        #pragma unroll
        for (int mi = 0; mi < 4; ++mi)
            LDSM4(a[0][mi][0], a[0][mi][1], a[0][mi][2], a[0][mi][3], baseA[mi] + stOff);
        #pragma unroll
        for (int p = 0; p < 4; ++p)
            LDSM4(b[0][2*p][0], b[0][2*p][1], b[0][2*p+1][0], b[0][2*p+1][1],
                  baseB[p] + stOff);

        // issue next gmem stage while fragments are in flight
        if (k + NSTAGE - 1 < NCHUNK)
            load_stage(smem_base, (k + NSTAGE - 1) & (NSTAGE - 1), k + NSTAGE - 1, gA, gB, tid);
        else
            asm volatile("cp.async.commit_group;");   // keep group count stable

        #pragma unroll
        for (int ki = 0; ki < 4; ++ki) {
            int cur = ki & 1, nxt = cur ^ 1;
            if (ki < 3) {                              // prefetch kstep ki+1
                uint32_t kx = (uint32_t)(ki + 1) << 5;
                #pragma unroll
                for (int mi = 0; mi < 4; ++mi)
                    LDSM4(a[nxt][mi][0], a[nxt][mi][1], a[nxt][mi][2], a[nxt][mi][3],
                          (baseA[mi] + stOff) ^ kx);
                #pragma unroll
                for (int p = 0; p < 4; ++p)
                    LDSM4(b[nxt][2*p][0], b[nxt][2*p][1], b[nxt][2*p+1][0], b[nxt][2*p+1][1],
                          (baseB[p] + stOff) ^ kx);
            }
            #pragma unroll
            for (int mi = 0; mi < 4; ++mi)
                #pragma unroll
                for (int ni = 0; ni < 8; ++ni) {
                    float* c = acc[mi][ni];
                    asm volatile(
                        "mma.sync.aligned.m16n8k16.row.col.f32.bf16.bf16.f32 "
                        "{%0,%1,%2,%3}, {%4,%5,%6,%7}, {%8,%9}, {%0,%1,%2,%3};"
                        : "+f"(c[0]), "+f"(c[1]), "+f"(c[2]), "+f"(c[3])
                        : "r"(a[cur][mi][0]), "r"(a[cur][mi][1]),
                          "r"(a[cur][mi][2]), "r"(a[cur][mi][3]),
                          "r"(b[cur][ni][0]), "r"(b[cur][ni][1]));
                }
        }
    }

    // ---- epilogue: per-row max of this 128x256 tile ----
    __syncthreads();
    if (tid < BM) smax[tid] = 0u;
    __syncthreads();

    #pragma unroll
    for (int mi = 0; mi < 4; ++mi) {
        float m0 = -3.402823466e38f, m1 = -3.402823466e38f;
        #pragma unroll
        for (int ni = 0; ni < 8; ++ni) {
            m0 = fmaxf(m0, fmaxf(acc[mi][ni][0], acc[mi][ni][1]));
            m1 = fmaxf(m1, fmaxf(acc[mi][ni][2], acc[mi][ni][3]));
        }
        m0 = fmaxf(m0, __shfl_xor_sync(0xffffffffu, m0, 1));
        m0 = fmaxf(m0, __shfl_xor_sync(0xffffffffu, m0, 2));
        m1 = fmaxf(m1, __shfl_xor_sync(0xffffffffu, m1, 1));
        m1 = fmaxf(m1, __shfl_xor_sync(0xffffffffu, m1, 2));
        if ((lane & 3) == 0) {
            int r = mb + mi * 16 + (lane >> 2);
            atomicMax(&smax[r], fkey(m0));
            atomicMax(&smax[r + 8], fkey(m1));
        }
    }
    __syncthreads();
    if (tid < BM) atomicMax(&g_rowmax[tileM * BM + tid], smax[tid]);
}

// ---------------- final: loss = mean(1 - rowmax) ----------------
__global__ void final_reduce_kernel(float* __restrict__ out) {
    __shared__ float red[256];
    int tid = threadIdx.x;
    float s = 0.f;
    for (int i = tid; i < N_DIM; i += 256) {
        unsigned int key = g_rowmax[i];
        float f = (key & 0x80000000u) ? __uint_as_float(key & 0x7FFFFFFFu)
                                      : __uint_as_float(~key);
        s += 1.0f - f;
    }
    red[tid] = s;
    __syncthreads();
    for (int off = 128; off > 0; off >>= 1) {
        if (tid < off) red[tid] += red[tid + off];
        __syncthreads();
    }
    if (tid == 0) out[0] = red[0] / (float)N_DIM;
}

// ---------------- launch ----------------
extern "C" void kernel_launch(void* const* d_in, const int* in_sizes, int n_in,
                              void* d_out, int out_size) {
    const float* F_r = (const float*)d_in[0];
    const float* F_s = (const float*)d_in[1];

    cudaFuncSetAttribute(nnfm_gemm_hmma, cudaFuncAttributeMaxDynamicSharedMemorySize, SMEM_TOTAL);

    init_rowmax_kernel<<<N_DIM / 256, 256>>>();
    colnorm_kernel<<<N_DIM / 64, 256>>>(F_r, 0);
    colnorm_kernel<<<N_DIM / 64, 256>>>(F_s, 1);

    dim3 tg(N_DIM / 64, C_DIM / 64);   // 256 x 12
    transpose_scale_kernel<<<tg, 256>>>(F_r, 0);
    transpose_scale_kernel<<<tg, 256>>>(F_s, 1);

    dim3 gg(N_DIM / BN, N_DIM / BM);   // 64 x 128
    nnfm_gemm_hmma<<<gg, 256, SMEM_TOTAL>>>();

    final_reduce_kernel<<<1, 256>>>((float*)d_out);
}